// round 6
// baseline (speedup 1.0000x reference)
#include <cuda_runtime.h>
#include <cstdint>
#include <cstddef>

#define MD   28          // matrix dim
#define D    784         // MD*MD
#define SEQ  128         // sequence length
#define NW   8           // warps per block == chain chunks
#define CLEN 16          // SEQ/NW matrices per warp
#define MAT_BYTES 3136   // D * 4
#define SMEM_BYTES (NW * 2 * MAT_BYTES)   // 50176 B of weight buffers (dynamic)

// ---------- packed f32x2 helpers (full fp32 precision, 2 FMA/instr) ----------
__device__ __forceinline__ unsigned long long pack2(float lo, float hi) {
    unsigned long long r;
    asm("mov.b64 %0, {%1, %2};" : "=l"(r) : "f"(lo), "f"(hi));
    return r;
}
__device__ __forceinline__ void unpack2(unsigned long long v, float& lo, float& hi) {
    asm("mov.b64 {%0, %1}, %2;" : "=f"(lo), "=f"(hi) : "l"(v));
}
__device__ __forceinline__ unsigned long long mul2(unsigned long long a, unsigned long long b) {
    unsigned long long r;
    asm("mul.rn.f32x2 %0, %1, %2;" : "=l"(r) : "l"(a), "l"(b));
    return r;
}
__device__ __forceinline__ void fma2(unsigned long long& d, unsigned long long a, unsigned long long b) {
    asm("fma.rn.f32x2 %0, %1, %2, %0;" : "+l"(d) : "l"(a), "l"(b));
}

// ---------- TMA bulk-copy + mbarrier helpers ----------
__device__ __forceinline__ unsigned s2u(const void* p) {
    return (unsigned)__cvta_generic_to_shared(p);
}
__device__ __forceinline__ void mbar_init(void* mbar) {
    asm volatile("mbarrier.init.shared.b64 [%0], %1;"
                 :: "r"(s2u(mbar)), "r"(1u) : "memory");
}
__device__ __forceinline__ void mbar_expect_tx(void* mbar, unsigned bytes) {
    asm volatile("mbarrier.arrive.expect_tx.shared.b64 _, [%0], %1;"
                 :: "r"(s2u(mbar)), "r"(bytes) : "memory");
}
__device__ __forceinline__ void mbar_wait(void* mbar, unsigned parity) {
    asm volatile(
        "{\n\t"
        ".reg .pred P;\n"
        "W%=:\n\t"
        "mbarrier.try_wait.parity.acquire.cta.shared::cta.b64 P, [%0], %1, 0x989680;\n\t"
        "@P bra D%=;\n\t"
        "bra W%=;\n"
        "D%=:\n\t"
        "}"
        :: "r"(s2u(mbar)), "r"(parity) : "memory");
}
__device__ __forceinline__ void bulk_cp(void* dst_smem, const void* src_gmem,
                                        unsigned bytes, void* mbar) {
    asm volatile(
        "cp.async.bulk.shared::cta.global.mbarrier::complete_tx::bytes [%0], [%1], %2, [%3];"
        :: "r"(s2u(dst_smem)), "l"(src_gmem), "r"(bytes), "r"(s2u(mbar)) : "memory");
}
__device__ __forceinline__ void fence_proxy_async_cta() {
    asm volatile("fence.proxy.async.shared::cta;" ::: "memory");
}

// cur (row i of running product, in regs) *= W, W in SHARED memory (broadcast LDS.128).
__device__ __forceinline__ void mm_step_s(float c[MD], const float4* __restrict__ w) {
    unsigned long long n2[14];
    #pragma unroll
    for (int k = 0; k < MD; ++k) {
        unsigned long long ck2 = pack2(c[k], c[k]);
        #pragma unroll
        for (int q = 0; q < 7; ++q) {
            float4 wv = w[k * 7 + q];
            unsigned long long wlo = pack2(wv.x, wv.y);
            unsigned long long whi = pack2(wv.z, wv.w);
            if (k == 0) {
                n2[2*q]   = mul2(ck2, wlo);
                n2[2*q+1] = mul2(ck2, whi);
            } else {
                fma2(n2[2*q],   ck2, wlo);
                fma2(n2[2*q+1], ck2, whi);
            }
        }
    }
    #pragma unroll
    for (int q = 0; q < 14; ++q) unpack2(n2[q], c[2*q], c[2*q+1]);
}

__device__ __forceinline__ void store_rows_f4(float4* dst7, const float c[MD]) {
    #pragma unroll
    for (int q = 0; q < 7; ++q)
        dst7[q] = make_float4(c[4*q], c[4*q+1], c[4*q+2], c[4*q+3]);
}

// One block per batch. 8 warps, each computes its 16-matrix chunk product with a
// private TMA double-buffered pipeline; 3-level smem tree combines the 8 partials.
__global__ void __launch_bounds__(NW * 32, 3)
w2m_fused(const int* __restrict__ sent, const float* __restrict__ tab,
          float* __restrict__ out)
{
    extern __shared__ float4 sbuf[];                    // [NW][2][196]
    __shared__ __align__(8) unsigned long long mbar[NW][2];

    int b    = blockIdx.x;
    int w    = (int)(threadIdx.x >> 5);
    int lane = (int)(threadIdx.x & 31);
    int i    = (lane < MD) ? lane : 0;   // lanes 28..31 shadow row 0

    float4* buf0 = sbuf + (w * 2 + 0) * 196;
    float4* buf1 = sbuf + (w * 2 + 1) * 196;

    if (lane == 0) {
        mbar_init(&mbar[w][0]);
        mbar_init(&mbar[w][1]);
        fence_proxy_async_cta();
    }
    __syncwarp();

    // one word index per lane for this warp's chunk (lanes 0..CLEN-1 valid)
    int sl  = (lane < CLEN) ? lane : 0;
    int idx = sent[b * SEQ + w * CLEN + sl];

    // kick off TMA for step 1 into buffer 1
    {
        int idx1 = __shfl_sync(0xffffffffu, idx, 1);
        if (lane == 0) {
            mbar_expect_tx(&mbar[w][1], MAT_BYTES);
            bulk_cp(buf1, tab + (size_t)idx1 * D, MAT_BYTES, &mbar[w][1]);
        }
    }

    // c = row i of matrix 0 (direct coalesced global load, latency paid once)
    float c[MD];
    {
        int idx0 = __shfl_sync(0xffffffffu, idx, 0);
        const float4* w0 = (const float4*)(tab + (size_t)idx0 * D) + i * 7;
        #pragma unroll
        for (int q = 0; q < 7; ++q) {
            float4 v = __ldg(w0 + q);
            c[4*q] = v.x; c[4*q+1] = v.y; c[4*q+2] = v.z; c[4*q+3] = v.w;
        }
    }

    unsigned ph0 = 0, ph1 = 0;   // per-buffer phase parity

    #pragma unroll 1
    for (int s = 1; s < CLEN; ++s) {
        if (s + 1 < CLEN) {
            int idxn = __shfl_sync(0xffffffffu, idx, s + 1);
            if (lane == 0) {
                void* mb = &mbar[w][(s + 1) & 1];
                mbar_expect_tx(mb, MAT_BYTES);
                bulk_cp(((s + 1) & 1) ? buf1 : buf0,
                        tab + (size_t)idxn * D, MAT_BYTES, mb);
            }
        }
        if (s & 1) { mbar_wait(&mbar[w][1], ph1); ph1 ^= 1u; }
        else       { mbar_wait(&mbar[w][0], ph0); ph0 ^= 1u; }
        mm_step_s(c, (s & 1) ? buf1 : buf0);
    }

    // ---- combine tree over 8 partials: pairs, quads, final ----
    float4* part = sbuf + (w * 2) * 196;                // partial of warp w lives in buf0 slot
    if (lane < MD)
        store_rows_f4((float4*)((float*)part + i * MD), c);
    __syncthreads();

    // level 1: even warps fold in odd neighbor: c = P_w * P_{w+1}
    if ((w & 1) == 0) {
        mm_step_s(c, sbuf + ((w + 1) * 2) * 196);
        if (w == 2 || w == 6) {
            if (lane < MD)
                store_rows_f4((float4*)((float*)(sbuf + (w * 2) * 196) + i * MD), c);
        }
    }
    __syncthreads();

    // level 2: warps 0 and 4 fold in the neighboring pair result
    if (w == 0) {
        mm_step_s(c, sbuf + (2 * 2) * 196);             // (P0P1)*(P2P3)
    } else if (w == 4) {
        mm_step_s(c, sbuf + (6 * 2) * 196);             // (P4P5)*(P6P7)
        if (lane < MD)
            store_rows_f4((float4*)((float*)(sbuf + (4 * 2) * 196) + i * MD), c);
    }
    __syncthreads();

    // level 3: warp 0 folds in the upper half and writes out
    if (w == 0) {
        mm_step_s(c, sbuf + (4 * 2) * 196);
        if (lane < MD)
            store_rows_f4((float4*)(out + (size_t)b * D + (size_t)i * MD), c);
    }
}

extern "C" void kernel_launch(void* const* d_in, const int* in_sizes, int n_in,
                              void* d_out, int out_size)
{
    const int*   sent;
    const float* tab;
    if (in_sizes[0] < in_sizes[1]) {
        sent = (const int*)d_in[0];
        tab  = (const float*)d_in[1];
    } else {
        sent = (const int*)d_in[1];
        tab  = (const float*)d_in[0];
    }
    int B = out_size / D;   // 512

    // >48KB dynamic smem needs an explicit opt-in (attribute set, not an allocation)
    static int smem_set = 0;
    if (!smem_set) {
        cudaFuncSetAttribute(w2m_fused,
                             cudaFuncAttributeMaxDynamicSharedMemorySize, SMEM_BYTES);
        smem_set = 1;
    }

    w2m_fused<<<B, NW * 32, SMEM_BYTES>>>(sent, tab, (float*)d_out);
}

// round 8
// speedup vs baseline: 1.3002x; 1.3002x over previous
#include <cuda_runtime.h>
#include <cstdint>
#include <cstddef>

#define MD   28
#define D    784
#define SEQ  128
#define NCH  8            // chunks per batch
#define CLEN 16           // matrices per chunk
#define NW   4            // warps/block; warp w: chunk 2w (low half), 2w+1 (high half)
#define MAT_BYTES 3136
#define SMEM_BYTES (NW * 2 * 2 * MAT_BYTES)   // [warp][chain][stage][196 float4] = 50176 B

// ---------- packed f32x2 helpers ----------
__device__ __forceinline__ unsigned long long pack2(float lo, float hi) {
    unsigned long long r;
    asm("mov.b64 %0, {%1, %2};" : "=l"(r) : "f"(lo), "f"(hi));
    return r;
}
__device__ __forceinline__ void unpack2(unsigned long long v, float& lo, float& hi) {
    asm("mov.b64 {%0, %1}, %2;" : "=f"(lo), "=f"(hi) : "l"(v));
}
__device__ __forceinline__ unsigned long long mul2(unsigned long long a, unsigned long long b) {
    unsigned long long r;
    asm("mul.rn.f32x2 %0, %1, %2;" : "=l"(r) : "l"(a), "l"(b));
    return r;
}
__device__ __forceinline__ void fma2(unsigned long long& d, unsigned long long a, unsigned long long b) {
    asm("fma.rn.f32x2 %0, %1, %2, %0;" : "+l"(d) : "l"(a), "l"(b));
}

// ---------- TMA bulk-copy + mbarrier helpers ----------
__device__ __forceinline__ unsigned s2u(const void* p) {
    return (unsigned)__cvta_generic_to_shared(p);
}
__device__ __forceinline__ void mbar_init(void* mbar) {
    asm volatile("mbarrier.init.shared.b64 [%0], %1;"
                 :: "r"(s2u(mbar)), "r"(1u) : "memory");
}
__device__ __forceinline__ void mbar_expect_tx(void* mbar, unsigned bytes) {
    asm volatile("mbarrier.arrive.expect_tx.shared.b64 _, [%0], %1;"
                 :: "r"(s2u(mbar)), "r"(bytes) : "memory");
}
__device__ __forceinline__ void mbar_wait(void* mbar, unsigned parity) {
    asm volatile(
        "{\n\t"
        ".reg .pred P;\n"
        "W%=:\n\t"
        "mbarrier.try_wait.parity.acquire.cta.shared::cta.b64 P, [%0], %1, 0x989680;\n\t"
        "@P bra D%=;\n\t"
        "bra W%=;\n"
        "D%=:\n\t"
        "}"
        :: "r"(s2u(mbar)), "r"(parity) : "memory");
}
__device__ __forceinline__ void bulk_cp(void* dst_smem, const void* src_gmem,
                                        unsigned bytes, void* mbar) {
    asm volatile(
        "cp.async.bulk.shared::cta.global.mbarrier::complete_tx::bytes [%0], [%1], %2, [%3];"
        :: "r"(s2u(dst_smem)), "l"(src_gmem), "r"(bytes), "r"(s2u(mbar)) : "memory");
}
__device__ __forceinline__ void fence_proxy_async_cta() {
    asm volatile("fence.proxy.async.shared::cta;" ::: "memory");
}

// Two rows per lane: {c0,c1} = rows sl and sl+14 of the running product.
// W in smem, broadcast per 16-lane half. Each LDS.128 feeds 4 FMA2.
__device__ __forceinline__ void mm_step2(float c0[MD], float c1[MD],
                                         const float4* __restrict__ w) {
    unsigned long long a0[14], a1[14];
    #pragma unroll
    for (int k = 0; k < MD; ++k) {
        unsigned long long k0 = pack2(c0[k], c0[k]);
        unsigned long long k1 = pack2(c1[k], c1[k]);
        #pragma unroll
        for (int q = 0; q < 7; ++q) {
            float4 wv = w[k * 7 + q];
            unsigned long long wlo = pack2(wv.x, wv.y);
            unsigned long long whi = pack2(wv.z, wv.w);
            if (k == 0) {
                a0[2*q]   = mul2(k0, wlo);
                a0[2*q+1] = mul2(k0, whi);
                a1[2*q]   = mul2(k1, wlo);
                a1[2*q+1] = mul2(k1, whi);
            } else {
                fma2(a0[2*q],   k0, wlo);
                fma2(a0[2*q+1], k0, whi);
                fma2(a1[2*q],   k1, wlo);
                fma2(a1[2*q+1], k1, whi);
            }
        }
    }
    #pragma unroll
    for (int q = 0; q < 14; ++q) {
        unpack2(a0[q], c0[2*q], c0[2*q+1]);
        unpack2(a1[q], c1[2*q], c1[2*q+1]);
    }
}

// store both rows of one lane into a 28x28 float tile
__device__ __forceinline__ void store2(float* tile, int r0, int r1,
                                       const float c0[MD], const float c1[MD]) {
    float4* p0 = (float4*)(tile + r0 * MD);
    float4* p1 = (float4*)(tile + r1 * MD);
    #pragma unroll
    for (int q = 0; q < 7; ++q) {
        p0[q] = make_float4(c0[4*q], c0[4*q+1], c0[4*q+2], c0[4*q+3]);
        p1[q] = make_float4(c1[4*q], c1[4*q+1], c1[4*q+2], c1[4*q+3]);
    }
}

// One block = one batch. Warp w runs chunks 2w (lanes 0-15) and 2w+1 (lanes 16-31),
// 2 rows per lane, per-chain TMA double buffers; 7-matmul combine tree.
__global__ void __launch_bounds__(NW * 32, 3)
w2m_fused(const int* __restrict__ sent, const float* __restrict__ tab,
          float* __restrict__ out)
{
    extern __shared__ float4 sbuf[];                // [NW][2 chains][2 stages][196]
    __shared__ __align__(8) unsigned long long mbar[NW][2];

    int b    = blockIdx.x;
    int w    = (int)(threadIdx.x >> 5);
    int lane = (int)(threadIdx.x & 31);
    int h    = lane >> 4;                           // half: 0 -> chunk 2w, 1 -> chunk 2w+1
    int sl   = lane & 15;                           // lane within half
    int act  = (sl < 14);                           // lanes 14,15 of each half idle
    int r0   = act ? sl : 0;
    int r1   = act ? sl + 14 : 0;

    float4* bufA0 = sbuf + ((w * 2 + 0) * 2 + 0) * 196;
    float4* bufA1 = sbuf + ((w * 2 + 0) * 2 + 1) * 196;
    float4* bufB0 = sbuf + ((w * 2 + 1) * 2 + 0) * 196;
    float4* bufB1 = sbuf + ((w * 2 + 1) * 2 + 1) * 196;
    // stage-0 buffers double as partial-product slots in the epilogue
    float* slotf = (float*)sbuf;
    auto slot = [&](int ww, int hh) -> float* {
        return slotf + (size_t)((ww * 2 + hh) * 2 + 0) * 196 * 4;
    };

    if (lane == 0) {
        mbar_init(&mbar[w][0]);
        mbar_init(&mbar[w][1]);
        fence_proxy_async_cta();
    }
    __syncwarp();

    // per-lane word indices for both chains of this warp (step = sl)
    int iA = sent[b * SEQ + (2 * w)     * CLEN + sl];
    int iB = sent[b * SEQ + (2 * w + 1) * CLEN + sl];

    // kick off TMA for step 1 of both chains into stage 1
    {
        int a1i = __shfl_sync(0xffffffffu, iA, 1);
        int b1i = __shfl_sync(0xffffffffu, iB, 1);
        if (lane == 0) {
            mbar_expect_tx(&mbar[w][1], 2 * MAT_BYTES);
            bulk_cp(bufA1, tab + (size_t)a1i * D, MAT_BYTES, &mbar[w][1]);
            bulk_cp(bufB1, tab + (size_t)b1i * D, MAT_BYTES, &mbar[w][1]);
        }
    }

    // c = rows r0,r1 of matrix 0 of this half's chain.
    // FIX (R7 bug): shuffle BOTH chains warp-wide, THEN select per-lane.
    // (shfl of `h ? iB : iA` returned lane0's value -> chain A for everyone.)
    float c0[MD], c1[MD];
    {
        int a0i = __shfl_sync(0xffffffffu, iA, 0);
        int b0i = __shfl_sync(0xffffffffu, iB, 0);
        int i0  = h ? b0i : a0i;
        const float4* w0 = (const float4*)(tab + (size_t)i0 * D);
        #pragma unroll
        for (int q = 0; q < 7; ++q) {
            float4 v0 = __ldg(w0 + r0 * 7 + q);
            float4 v1 = __ldg(w0 + r1 * 7 + q);
            c0[4*q] = v0.x; c0[4*q+1] = v0.y; c0[4*q+2] = v0.z; c0[4*q+3] = v0.w;
            c1[4*q] = v1.x; c1[4*q+1] = v1.y; c1[4*q+2] = v1.z; c1[4*q+3] = v1.w;
        }
    }

    unsigned ph0 = 0, ph1 = 0;

    #pragma unroll 1
    for (int s = 1; s < CLEN; ++s) {
        if (s + 1 < CLEN) {
            int an = __shfl_sync(0xffffffffu, iA, s + 1);
            int bn = __shfl_sync(0xffffffffu, iB, s + 1);
            if (lane == 0) {
                int st = (s + 1) & 1;
                void* mb = &mbar[w][st];
                mbar_expect_tx(mb, 2 * MAT_BYTES);
                bulk_cp(st ? bufA1 : bufA0, tab + (size_t)an * D, MAT_BYTES, mb);
                bulk_cp(st ? bufB1 : bufB0, tab + (size_t)bn * D, MAT_BYTES, mb);
            }
        }
        if (s & 1) { mbar_wait(&mbar[w][1], ph1); ph1 ^= 1u; }
        else       { mbar_wait(&mbar[w][0], ph0); ph0 ^= 1u; }
        const float4* wp = (s & 1) ? (h ? bufB1 : bufA1) : (h ? bufB0 : bufA0);
        mm_step2(c0, c1, wp);
    }

    // ---- combine tree: 8 partials -> 1 ----
    if (h == 1 && act) store2(slot(w, 1), r0, r1, c0, c1);
    __syncthreads();

    // level 1: Q_w = P_{2w} * P_{2w+1}
    mm_step2(c0, c1, (const float4*)slot(w, 1));
    if (h == 0 && act && (w == 1 || w == 3)) store2(slot(w, 0), r0, r1, c0, c1);
    __syncthreads();

    // level 2: R0 = Q0*Q1 (warp 0), R1 = Q2*Q3 (warp 2)
    if (w == 0) {
        mm_step2(c0, c1, (const float4*)slot(1, 0));
    } else if (w == 2) {
        mm_step2(c0, c1, (const float4*)slot(3, 0));
        if (h == 0 && act) store2(slot(2, 0), r0, r1, c0, c1);
    }
    __syncthreads();

    // level 3: out = R0 * R1 (warp 0, low half writes)
    if (w == 0) {
        mm_step2(c0, c1, (const float4*)slot(2, 0));
        if (h == 0 && act)
            store2(out + (size_t)b * D, r0, r1, c0, c1);
    }
}

extern "C" void kernel_launch(void* const* d_in, const int* in_sizes, int n_in,
                              void* d_out, int out_size)
{
    const int*   sent;
    const float* tab;
    if (in_sizes[0] < in_sizes[1]) {
        sent = (const int*)d_in[0];
        tab  = (const float*)d_in[1];
    } else {
        sent = (const int*)d_in[1];
        tab  = (const float*)d_in[0];
    }
    int B = out_size / D;   // 512

    static int smem_set = 0;
    if (!smem_set) {
        cudaFuncSetAttribute(w2m_fused,
                             cudaFuncAttributeMaxDynamicSharedMemorySize, SMEM_BYTES);
        smem_set = 1;
    }

    w2m_fused<<<B, NW * 32, SMEM_BYTES>>>(sent, tab, (float*)d_out);
}